// round 6
// baseline (speedup 1.0000x reference)
#include <cuda_runtime.h>
#include <cstdint>

#define N_TASKS   8
#define D_MODEL   1024
#define HIDDEN    1024
#define N_CLASSES 100
#define BATCH     8192

#define BM 128
#define BN 128
#define BK 16
#define NTHREADS 256

#define AS_STRIDE 20    // words per As row -> conflict-free frag reads
#define BS_STRIDE 136   // words per Bs row -> conflict-free frag reads

// Scratch (device globals; no allocation allowed in kernel_launch).
// NOTE: these must ONLY be referenced from device code. Passing a __device__
// symbol as a host-side kernel argument passes the host shadow address, which
// GB300's ATS will silently dereference — that was the round-2 bug.
__device__ int   d_perm[BATCH];
__device__ int   d_off[N_TASKS + 1];
__device__ float d_H[(size_t)BATCH * HIDDEN];   // hidden activations, task-compact

// ---------------------------------------------------------------------------
__global__ void bin_kernel(const int* __restrict__ task_id) {
    __shared__ int s_cnt[N_TASKS];
    __shared__ int s_off[N_TASKS + 1];
    __shared__ int s_cur[N_TASKS];
    int tid = threadIdx.x;
    if (tid < N_TASKS) { s_cnt[tid] = 0; s_cur[tid] = 0; }
    __syncthreads();
    for (int i = tid; i < BATCH; i += blockDim.x)
        atomicAdd(&s_cnt[task_id[i]], 1);
    __syncthreads();
    if (tid == 0) {
        int acc = 0;
        for (int t = 0; t < N_TASKS; t++) { s_off[t] = acc; acc += s_cnt[t]; }
        s_off[N_TASKS] = acc;
    }
    __syncthreads();
    if (tid <= N_TASKS) d_off[tid] = s_off[tid];
    for (int i = tid; i < BATCH; i += blockDim.x) {
        int t = task_id[i];
        int pos = s_off[t] + atomicAdd(&s_cur[t], 1);
        d_perm[pos] = i;
    }
}

// ---------------------------------------------------------------------------
__device__ __forceinline__ uint32_t f2tf32(float f) {
    uint32_t r;
    asm("cvt.rna.tf32.f32 %0, %1;" : "=r"(r) : "f"(f));
    return r;
}

__device__ __forceinline__ void mma_tf32(float c[4],
                                         uint32_t a0, uint32_t a1, uint32_t a2, uint32_t a3,
                                         uint32_t b0, uint32_t b1) {
    asm volatile(
        "mma.sync.aligned.m16n8k8.row.col.f32.tf32.tf32.f32 "
        "{%0,%1,%2,%3}, {%4,%5,%6,%7}, {%8,%9}, {%0,%1,%2,%3};"
        : "+f"(c[0]), "+f"(c[1]), "+f"(c[2]), "+f"(c[3])
        : "r"(a0), "r"(a1), "r"(a2), "r"(a3), "r"(b0), "r"(b1));
}

// ---------------------------------------------------------------------------
// tf32 GEMM core with register-prefetch pipelining.
// C tile = BM x BN, 8 warps in 2(M) x 4(N), warp tile 64x32, 4x4 m16n8k8.
//
// LAYER=1: A = x gathered via d_perm, B = W1 (ld 1024), epi relu+b1 -> d_H
// LAYER=2: A = d_H (device symbol, read in-kernel), B = W2 (ld 100, padded),
//          epi +b2, scatter rows via d_perm, cols < 100.
// ---------------------------------------------------------------------------
template <int LAYER>
__global__ void __launch_bounds__(NTHREADS, 2)
gemm_tf32_kernel(const float* __restrict__ x,
                 const float* __restrict__ Wsrc,
                 const float* __restrict__ bias,
                 float* __restrict__ out) {
    const int task = blockIdx.z;
    const int m0   = d_off[task];
    const int rows = d_off[task + 1] - m0;
    const int rowTile = blockIdx.y;
    if (rowTile * BM >= rows) return;
    const int colTile = blockIdx.x;

    constexpr int KDIM = (LAYER == 1) ? D_MODEL : HIDDEN;
    constexpr int LDB  = (LAYER == 1) ? HIDDEN  : N_CLASSES;
    const float* __restrict__ W = Wsrc + (size_t)task * KDIM * LDB;

    __shared__ uint32_t As[BM * AS_STRIDE];
    __shared__ uint32_t Bs[BK * BS_STRIDE];

    const int tid  = threadIdx.x;
    const int lane = tid & 31;
    const int warpId = tid >> 5;
    const int warpM = warpId >> 2;       // 0..1
    const int warpN = warpId & 3;        // 0..3
    const int gid   = lane >> 2;         // 0..7
    const int tig   = lane & 3;          // 0..3

    // ---- global->smem load mapping ----
    const int aRow0 = tid >> 2;              // 0..63
    const int aK    = (tid & 3) * 4;
    const int r0 = rowTile * BM + aRow0;
    const int r1 = r0 + 64;
    const bool v0 = (r0 < rows), v1 = (r1 < rows);
    const float* pA0;
    const float* pA1;
    if (LAYER == 1) {
        pA0 = v0 ? (x + (size_t)d_perm[m0 + r0] * D_MODEL) : x;
        pA1 = v1 ? (x + (size_t)d_perm[m0 + r1] * D_MODEL) : x;
    } else {
        pA0 = d_H + (size_t)(m0 + (v0 ? r0 : 0)) * HIDDEN;   // device symbol, in-kernel
        pA1 = d_H + (size_t)(m0 + (v1 ? r1 : 0)) * HIDDEN;
    }
    const int bK    = tid >> 5;              // 0..7
    const int bCol  = (tid & 31) * 4;
    const int colBaseB = colTile * BN + bCol;
    const bool wValid2 = (bCol + 3 < N_CLASSES);   // layer-2 B pad predicate

    float acc[4][4][4] = {};  // [mtile][ntile][reg]
    const float4 zero4 = make_float4(0.f, 0.f, 0.f, 0.f);

    // ---- prefetch registers for tile k0 ----
    float4 fa0, fa1, fb0, fb1;
    {
        fa0 = v0 ? *reinterpret_cast<const float4*>(pA0 + aK) : zero4;
        fa1 = v1 ? *reinterpret_cast<const float4*>(pA1 + aK) : zero4;
        if (LAYER == 1) {
            fb0 = *reinterpret_cast<const float4*>(W + (size_t)(bK    ) * LDB + colBaseB);
            fb1 = *reinterpret_cast<const float4*>(W + (size_t)(bK + 8) * LDB + colBaseB);
        } else {
            fb0 = wValid2 ? *reinterpret_cast<const float4*>(W + (size_t)(bK    ) * LDB + bCol) : zero4;
            fb1 = wValid2 ? *reinterpret_cast<const float4*>(W + (size_t)(bK + 8) * LDB + bCol) : zero4;
        }
    }

    for (int k0 = 0; k0 < KDIM; k0 += BK) {
        // --- commit prefetched tile to smem (tf32 convert at store) ---
        {
            uint32_t* s = &As[aRow0 * AS_STRIDE + aK];
            s[0] = f2tf32(fa0.x); s[1] = f2tf32(fa0.y); s[2] = f2tf32(fa0.z); s[3] = f2tf32(fa0.w);
            uint32_t* s2 = &As[(aRow0 + 64) * AS_STRIDE + aK];
            s2[0] = f2tf32(fa1.x); s2[1] = f2tf32(fa1.y); s2[2] = f2tf32(fa1.z); s2[3] = f2tf32(fa1.w);
            uint32_t* sb0 = &Bs[bK * BS_STRIDE + bCol];
            sb0[0] = f2tf32(fb0.x); sb0[1] = f2tf32(fb0.y); sb0[2] = f2tf32(fb0.z); sb0[3] = f2tf32(fb0.w);
            uint32_t* sb1 = &Bs[(bK + 8) * BS_STRIDE + bCol];
            sb1[0] = f2tf32(fb1.x); sb1[1] = f2tf32(fb1.y); sb1[2] = f2tf32(fb1.z); sb1[3] = f2tf32(fb1.w);
        }
        __syncthreads();

        // --- issue next tile's global loads; latency drains behind the MMAs ---
        const int kn = k0 + BK;
        if (kn < KDIM) {
            fa0 = v0 ? *reinterpret_cast<const float4*>(pA0 + kn + aK) : zero4;
            fa1 = v1 ? *reinterpret_cast<const float4*>(pA1 + kn + aK) : zero4;
            if (LAYER == 1) {
                fb0 = *reinterpret_cast<const float4*>(W + (size_t)(kn + bK    ) * LDB + colBaseB);
                fb1 = *reinterpret_cast<const float4*>(W + (size_t)(kn + bK + 8) * LDB + colBaseB);
            } else {
                fb0 = wValid2 ? *reinterpret_cast<const float4*>(W + (size_t)(kn + bK    ) * LDB + bCol) : zero4;
                fb1 = wValid2 ? *reinterpret_cast<const float4*>(W + (size_t)(kn + bK + 8) * LDB + bCol) : zero4;
            }
        }

        // --- compute: 2 k8 steps ---
        #pragma unroll
        for (int s = 0; s < 2; s++) {
            const int kb = s * 8;
            uint32_t af[4][4];
            #pragma unroll
            for (int i = 0; i < 4; i++) {
                int row = warpM * 64 + i * 16 + gid;
                const uint32_t* p = &As[row * AS_STRIDE + kb + tig];
                af[i][0] = p[0];
                af[i][1] = p[8 * AS_STRIDE];
                af[i][2] = p[4];
                af[i][3] = p[8 * AS_STRIDE + 4];
            }
            uint32_t bf[4][2];
            #pragma unroll
            for (int j = 0; j < 4; j++) {
                int col = warpN * 32 + j * 8 + gid;
                const uint32_t* p = &Bs[(kb + tig) * BS_STRIDE + col];
                bf[j][0] = p[0];
                bf[j][1] = p[4 * BS_STRIDE];
            }
            #pragma unroll
            for (int i = 0; i < 4; i++)
                #pragma unroll
                for (int j = 0; j < 4; j++)
                    mma_tf32(acc[i][j], af[i][0], af[i][1], af[i][2], af[i][3],
                             bf[j][0], bf[j][1]);
        }
        __syncthreads();
    }

    // ---- epilogue ----
    #pragma unroll
    for (int i = 0; i < 4; i++) {
        #pragma unroll
        for (int j = 0; j < 4; j++) {
            int colLoc = warpN * 32 + j * 8 + 2 * tig;
            int col = colTile * BN + colLoc;
            #pragma unroll
            for (int half = 0; half < 2; half++) {
                int r = rowTile * BM + warpM * 64 + i * 16 + gid + half * 8;
                if (r >= rows) continue;
                float v0c = acc[i][j][half * 2 + 0];
                float v1c = acc[i][j][half * 2 + 1];
                if (LAYER == 1) {
                    float bb0 = bias[(size_t)task * HIDDEN + col];
                    float bb1 = bias[(size_t)task * HIDDEN + col + 1];
                    float2 v;
                    v.x = fmaxf(v0c + bb0, 0.f);
                    v.y = fmaxf(v1c + bb1, 0.f);
                    *reinterpret_cast<float2*>(d_H + (size_t)(m0 + r) * HIDDEN + col) = v;
                } else {
                    int orig = d_perm[m0 + r];
                    float* op = out + (size_t)orig * N_CLASSES;
                    if (col < N_CLASSES)
                        op[col] = v0c + bias[(size_t)task * N_CLASSES + col];
                    if (col + 1 < N_CLASSES)
                        op[col + 1] = v1c + bias[(size_t)task * N_CLASSES + col + 1];
                }
            }
        }
    }
}

extern "C" void kernel_launch(void* const* d_in, const int* in_sizes, int n_in,
                              void* d_out, int out_size) {
    const float* x       = (const float*)d_in[0];
    const int*   task_id = (const int*)  d_in[1];
    const float* W1      = (const float*)d_in[2];
    const float* b1      = (const float*)d_in[3];
    const float* W2      = (const float*)d_in[4];
    const float* b2      = (const float*)d_in[5];
    float*       out     = (float*)d_out;

    bin_kernel<<<1, 256>>>(task_id);

    // Layer 1: H = relu(x @ W1 + b1), grouped by task
    dim3 g1(HIDDEN / BN, (BATCH + BM - 1) / BM, N_TASKS);
    gemm_tf32_kernel<1><<<g1, NTHREADS>>>(x, W1, b1, nullptr);

    // Layer 2: out = H @ W2 + b2 (N=100 in one 128-wide tile), scatter rows
    dim3 g2(1, (BATCH + BM - 1) / BM, N_TASKS);
    gemm_tf32_kernel<2><<<g2, NTHREADS>>>(x, W2, b2, out);
}

// round 7
// speedup vs baseline: 1.2576x; 1.2576x over previous
#include <cuda_runtime.h>
#include <cstdint>

#define N_TASKS   8
#define D_MODEL   1024
#define HIDDEN    1024
#define N_CLASSES 100
#define BATCH     8192

#define BM 128
#define BN 128
#define BK 16
#define NTHREADS 256
#define KSPLIT   4
#define CHUNK    (HIDDEN / KSPLIT)   // 256

#define AS_STRIDE 20    // words per As row -> conflict-free frag reads
#define BS_STRIDE 136   // words per Bs row -> conflict-free frag reads

// Scratch (device globals). Only referenced from device code — passing a
// __device__ symbol as a host-side kernel arg passes the host shadow address,
// which GB300's ATS silently dereferences (the round-2 bug).
__device__ int   d_perm[BATCH];
__device__ int   d_off[N_TASKS + 1];
__device__ float d_H[(size_t)BATCH * HIDDEN];          // hidden acts, task-compact
__device__ float d_P[KSPLIT][BATCH][128];              // layer-2 split-K partials

// ---------------------------------------------------------------------------
// Binning: 1024 threads, warp-aggregated atomics (one atomic per warp per task).
// Order within a task is nondeterministic but the final output is invariant.
// ---------------------------------------------------------------------------
__global__ void bin_kernel(const int* __restrict__ task_id) {
    __shared__ int s_cnt[N_TASKS];
    __shared__ int s_base[N_TASKS + 1];
    __shared__ int s_cur[N_TASKS];
    const int tid = threadIdx.x;
    if (tid < N_TASKS) { s_cnt[tid] = 0; s_cur[tid] = 0; }
    __syncthreads();
    for (int i = tid; i < BATCH; i += 1024) {
        int t = task_id[i];
        unsigned m = __match_any_sync(0xffffffffu, t);
        int leader = __ffs(m) - 1;
        if ((int)(tid & 31) == leader) atomicAdd(&s_cnt[t], __popc(m));
    }
    __syncthreads();
    if (tid == 0) {
        int acc = 0;
        for (int t = 0; t < N_TASKS; t++) { s_base[t] = acc; acc += s_cnt[t]; }
        s_base[N_TASKS] = acc;
    }
    __syncthreads();
    if (tid <= N_TASKS) d_off[tid] = s_base[tid];
    for (int i = tid; i < BATCH; i += 1024) {
        int t = task_id[i];
        unsigned m = __match_any_sync(0xffffffffu, t);
        int lane = tid & 31;
        int leader = __ffs(m) - 1;
        int rank = __popc(m & ((1u << lane) - 1u));
        int base = 0;
        if (lane == leader) base = atomicAdd(&s_cur[t], __popc(m));
        base = __shfl_sync(m, base, leader);
        d_perm[s_base[t] + base + rank] = i;
    }
}

// ---------------------------------------------------------------------------
__device__ __forceinline__ uint32_t f2tf32(float f) {
    uint32_t r;
    asm("cvt.rna.tf32.f32 %0, %1;" : "=r"(r) : "f"(f));
    return r;
}

__device__ __forceinline__ void mma_tf32(float c[4],
                                         uint32_t a0, uint32_t a1, uint32_t a2, uint32_t a3,
                                         uint32_t b0, uint32_t b1) {
    asm volatile(
        "mma.sync.aligned.m16n8k8.row.col.f32.tf32.tf32.f32 "
        "{%0,%1,%2,%3}, {%4,%5,%6,%7}, {%8,%9}, {%0,%1,%2,%3};"
        : "+f"(c[0]), "+f"(c[1]), "+f"(c[2]), "+f"(c[3])
        : "r"(a0), "r"(a1), "r"(a2), "r"(a3), "r"(b0), "r"(b1));
}

__device__ __forceinline__ uint4 tf32x4(float4 v) {
    uint4 u;
    u.x = f2tf32(v.x); u.y = f2tf32(v.y); u.z = f2tf32(v.z); u.w = f2tf32(v.w);
    return u;
}

// ---------------------------------------------------------------------------
// Double-buffered tf32 GEMM core. C tile BM x BN, 8 warps 2(M) x 4(N),
// warp tile 64x32, 4x4 m16n8k8. One __syncthreads per K-tile.
//
// LAYER=1: blockIdx.x = colTile; A = x gathered via d_perm; B = W1;
//          K = [0, 1024); epi relu+b1 -> d_H (compact).
// LAYER=2: blockIdx.x = K-split index; A = d_H; B = W2 (cols padded to 128);
//          K = [split*256, +256); raw partial -> d_P[split] (no bias).
// ---------------------------------------------------------------------------
template <int LAYER>
__global__ void __launch_bounds__(NTHREADS, 2)
gemm_tf32_kernel(const float* __restrict__ x,
                 const float* __restrict__ Wsrc,
                 const float* __restrict__ bias,
                 float* __restrict__ out) {
    const int task = blockIdx.z;
    const int m0   = d_off[task];
    const int rows = d_off[task + 1] - m0;
    const int rowTile = blockIdx.y;
    if (rowTile * BM >= rows) return;

    const int colTile = (LAYER == 1) ? blockIdx.x : 0;
    const int kbase   = (LAYER == 1) ? 0 : blockIdx.x * CHUNK;
    const int kend    = (LAYER == 1) ? D_MODEL : kbase + CHUNK;

    constexpr int KD  = (LAYER == 1) ? D_MODEL : HIDDEN;   // A leading dim
    constexpr int LDB = (LAYER == 1) ? HIDDEN  : N_CLASSES;
    const float* __restrict__ W = Wsrc + (size_t)task * KD * LDB;

    __shared__ uint32_t As[2][BM * AS_STRIDE];
    __shared__ uint32_t Bs[2][BK * BS_STRIDE];

    const int tid  = threadIdx.x;
    const int lane = tid & 31;
    const int warpId = tid >> 5;
    const int warpM = warpId >> 2;       // 0..1
    const int warpN = warpId & 3;        // 0..3
    const int gid   = lane >> 2;         // 0..7
    const int tig   = lane & 3;          // 0..3

    // ---- global->smem load mapping ----
    const int aRow0 = tid >> 2;              // 0..63
    const int aK    = (tid & 3) * 4;
    const int r0 = rowTile * BM + aRow0;
    const int r1 = r0 + 64;
    const bool v0 = (r0 < rows), v1 = (r1 < rows);
    const float* pA0;
    const float* pA1;
    if (LAYER == 1) {
        pA0 = v0 ? (x + (size_t)d_perm[m0 + r0] * D_MODEL) : x;
        pA1 = v1 ? (x + (size_t)d_perm[m0 + r1] * D_MODEL) : x;
    } else {
        pA0 = d_H + (size_t)(m0 + (v0 ? r0 : 0)) * HIDDEN;
        pA1 = d_H + (size_t)(m0 + (v1 ? r1 : 0)) * HIDDEN;
    }
    const int bK    = tid >> 5;              // 0..7
    const int bCol  = (tid & 31) * 4;
    const int colBaseB = colTile * BN + bCol;
    const bool wValid2 = (bCol + 3 < N_CLASSES);

    float acc[4][4][4] = {};
    const float4 zero4 = make_float4(0.f, 0.f, 0.f, 0.f);

    // lambda-free load helper (macros of indices)
    float4 fa0, fa1, fb0, fb1;
    auto load_tile = [&](int k0) {
        fa0 = v0 ? *reinterpret_cast<const float4*>(pA0 + k0 + aK) : zero4;
        fa1 = v1 ? *reinterpret_cast<const float4*>(pA1 + k0 + aK) : zero4;
        if (LAYER == 1) {
            fb0 = *reinterpret_cast<const float4*>(W + (size_t)(k0 + bK    ) * LDB + colBaseB);
            fb1 = *reinterpret_cast<const float4*>(W + (size_t)(k0 + bK + 8) * LDB + colBaseB);
        } else {
            fb0 = wValid2 ? *reinterpret_cast<const float4*>(W + (size_t)(k0 + bK    ) * LDB + bCol) : zero4;
            fb1 = wValid2 ? *reinterpret_cast<const float4*>(W + (size_t)(k0 + bK + 8) * LDB + bCol) : zero4;
        }
    };
    auto store_tile = [&](int buf) {
        // uint4 STS.128 fills (conflict-free for B; mild 2-way on A, acceptable)
        *reinterpret_cast<uint4*>(&As[buf][aRow0 * AS_STRIDE + aK])        = tf32x4(fa0);
        *reinterpret_cast<uint4*>(&As[buf][(aRow0 + 64) * AS_STRIDE + aK]) = tf32x4(fa1);
        *reinterpret_cast<uint4*>(&Bs[buf][bK * BS_STRIDE + bCol])         = tf32x4(fb0);
        *reinterpret_cast<uint4*>(&Bs[buf][(bK + 8) * BS_STRIDE + bCol])   = tf32x4(fb1);
    };

    load_tile(kbase);
    store_tile(0);
    __syncthreads();

    int cur = 0;
    for (int k0 = kbase; k0 < kend; k0 += BK) {
        const int kn = k0 + BK;
        if (kn < kend) load_tile(kn);          // LDG latency drains behind MMAs

        const uint32_t* __restrict__ Ac = As[cur];
        const uint32_t* __restrict__ Bc = Bs[cur];
        #pragma unroll
        for (int s = 0; s < 2; s++) {
            const int kb = s * 8;
            uint32_t af[4][4];
            #pragma unroll
            for (int i = 0; i < 4; i++) {
                int row = warpM * 64 + i * 16 + gid;
                const uint32_t* p = &Ac[row * AS_STRIDE + kb + tig];
                af[i][0] = p[0];
                af[i][1] = p[8 * AS_STRIDE];
                af[i][2] = p[4];
                af[i][3] = p[8 * AS_STRIDE + 4];
            }
            uint32_t bf[4][2];
            #pragma unroll
            for (int j = 0; j < 4; j++) {
                int col = warpN * 32 + j * 8 + gid;
                const uint32_t* p = &Bc[(kb + tig) * BS_STRIDE + col];
                bf[j][0] = p[0];
                bf[j][1] = p[4 * BS_STRIDE];
            }
            #pragma unroll
            for (int i = 0; i < 4; i++)
                #pragma unroll
                for (int j = 0; j < 4; j++)
                    mma_tf32(acc[i][j], af[i][0], af[i][1], af[i][2], af[i][3],
                             bf[j][0], bf[j][1]);
        }

        if (kn < kend) store_tile(cur ^ 1);    // other buffer: no race with readers
        __syncthreads();
        cur ^= 1;
    }

    // ---- epilogue ----
    #pragma unroll
    for (int i = 0; i < 4; i++) {
        #pragma unroll
        for (int j = 0; j < 4; j++) {
            int colLoc = warpN * 32 + j * 8 + 2 * tig;
            int col = colTile * BN + colLoc;
            #pragma unroll
            for (int half = 0; half < 2; half++) {
                int r = rowTile * BM + warpM * 64 + i * 16 + gid + half * 8;
                if (r >= rows) continue;
                float v0c = acc[i][j][half * 2 + 0];
                float v1c = acc[i][j][half * 2 + 1];
                if (LAYER == 1) {
                    float bb0 = bias[(size_t)task * HIDDEN + col];
                    float bb1 = bias[(size_t)task * HIDDEN + col + 1];
                    float2 v;
                    v.x = fmaxf(v0c + bb0, 0.f);
                    v.y = fmaxf(v1c + bb1, 0.f);
                    *reinterpret_cast<float2*>(d_H + (size_t)(m0 + r) * HIDDEN + col) = v;
                } else {
                    float2 v; v.x = v0c; v.y = v1c;
                    *reinterpret_cast<float2*>(&d_P[blockIdx.x][m0 + r][colLoc]) = v;
                }
            }
        }
    }
}

// ---------------------------------------------------------------------------
// Split-K reduction: out[perm[g], c] = sum_s d_P[s][g][c] + b2[task(g), c].
// Fixed summation order -> deterministic. One float4 (4 classes) per thread.
// ---------------------------------------------------------------------------
__global__ void reduce_kernel(const float* __restrict__ b2,
                              float* __restrict__ out) {
    const int idx = blockIdx.x * blockDim.x + threadIdx.x;
    if (idx >= BATCH * (N_CLASSES / 4)) return;
    const int g = idx / (N_CLASSES / 4);
    const int c = (idx % (N_CLASSES / 4)) * 4;

    float4 s = *reinterpret_cast<const float4*>(&d_P[0][g][c]);
    #pragma unroll
    for (int k = 1; k < KSPLIT; k++) {
        float4 p = *reinterpret_cast<const float4*>(&d_P[k][g][c]);
        s.x += p.x; s.y += p.y; s.z += p.z; s.w += p.w;
    }
    int t = 0;
    #pragma unroll
    for (int q = 1; q < N_TASKS; q++) t += (g >= d_off[q]);
    float4 bb = *reinterpret_cast<const float4*>(b2 + (size_t)t * N_CLASSES + c);
    s.x += bb.x; s.y += bb.y; s.z += bb.z; s.w += bb.w;

    const int orig = d_perm[g];
    *reinterpret_cast<float4*>(out + (size_t)orig * N_CLASSES + c) = s;
}

extern "C" void kernel_launch(void* const* d_in, const int* in_sizes, int n_in,
                              void* d_out, int out_size) {
    const float* x       = (const float*)d_in[0];
    const int*   task_id = (const int*)  d_in[1];
    const float* W1      = (const float*)d_in[2];
    const float* b1      = (const float*)d_in[3];
    const float* W2      = (const float*)d_in[4];
    const float* b2      = (const float*)d_in[5];
    float*       out     = (float*)d_out;

    bin_kernel<<<1, 1024>>>(task_id);

    dim3 g1(HIDDEN / BN, (BATCH + BM - 1) / BM, N_TASKS);
    gemm_tf32_kernel<1><<<g1, NTHREADS>>>(x, W1, b1, nullptr);

    dim3 g2(KSPLIT, (BATCH + BM - 1) / BM, N_TASKS);
    gemm_tf32_kernel<2><<<g2, NTHREADS>>>(x, W2, nullptr, nullptr);

    int nred = BATCH * (N_CLASSES / 4);
    reduce_kernel<<<(nred + 255) / 256, 256>>>(b2, out);
}